// round 13
// baseline (speedup 1.0000x reference)
#include <cuda_runtime.h>
#include <cstdint>

#define BB 64      // batch
#define TT 1024    // time steps
#define EE 512     // embedding
#define VV 256     // vocab

typedef unsigned long long ull;

// ---------------- device scratch ----------------
__device__ float g_xwv[VV * EE];                 // XWV[v][o] = emb[v]·w_x[o] + b_cell[o]
__device__ float g_hs[(size_t)BB * TT * EE];     // h_t, layout [b][t][e]  (128 MB)

// ---------------- helpers ----------------
__device__ __forceinline__ ull ffma2(ull a, ull b, ull c) {
    ull d;
    asm("fma.rn.f32x2 %0, %1, %2, %3;" : "=l"(d) : "l"(a), "l"(b), "l"(c));
    return d;
}
__device__ __forceinline__ ull fdup(float s) {
    ull d;
    asm("mov.b64 %0, {%1, %1};" : "=l"(d) : "f"(s));
    return d;
}
__device__ __forceinline__ float2 unpack2(ull v) {
    float2 r;
    asm("mov.b64 {%0, %1}, %2;" : "=f"(r.x), "=f"(r.y) : "l"(v));
    return r;
}
__device__ __forceinline__ uint32_t smem_u32(const void* p) {
    uint32_t a;
    asm("{ .reg .u64 t; cvta.to.shared.u64 t, %1; cvt.u32.u64 %0, t; }"
        : "=r"(a) : "l"(p));
    return a;
}

// =====================================================================
// Phase-1 GEMM (tiny):  C[M][N] = A[M][K] @ B[N][K]^T + bias[N]
// =====================================================================
__global__ void gemm_atb(const float* __restrict__ A, int lda,
                         const float* __restrict__ Bm, int ldb,
                         const float* __restrict__ bias,
                         float* __restrict__ C, int N, int K)
{
    __shared__ float As[16][64];
    __shared__ float Bs[16][64];

    const int tid  = threadIdx.x;
    const int m0   = blockIdx.x * 64;
    const int n0   = blockIdx.y * 64;
    const int tx   = tid & 15;
    const int ty   = tid >> 4;
    const int lrow = tid >> 2;
    const int lcol = (tid & 3) * 4;

    float acc[4][4];
#pragma unroll
    for (int i = 0; i < 4; ++i)
#pragma unroll
        for (int j = 0; j < 4; ++j) acc[i][j] = 0.0f;

    for (int k0 = 0; k0 < K; k0 += 16) {
        float4 av = *reinterpret_cast<const float4*>(A  + (size_t)(m0 + lrow) * lda + k0 + lcol);
        float4 bv = *reinterpret_cast<const float4*>(Bm + (size_t)(n0 + lrow) * ldb + k0 + lcol);
        As[lcol + 0][lrow] = av.x;  As[lcol + 1][lrow] = av.y;
        As[lcol + 2][lrow] = av.z;  As[lcol + 3][lrow] = av.w;
        Bs[lcol + 0][lrow] = bv.x;  Bs[lcol + 1][lrow] = bv.y;
        Bs[lcol + 2][lrow] = bv.z;  Bs[lcol + 3][lrow] = bv.w;
        __syncthreads();
#pragma unroll
        for (int kk = 0; kk < 16; ++kk) {
            float4 a = *reinterpret_cast<const float4*>(&As[kk][ty * 4]);
            float4 b = *reinterpret_cast<const float4*>(&Bs[kk][tx * 4]);
            acc[0][0] = fmaf(a.x, b.x, acc[0][0]); acc[0][1] = fmaf(a.x, b.y, acc[0][1]);
            acc[0][2] = fmaf(a.x, b.z, acc[0][2]); acc[0][3] = fmaf(a.x, b.w, acc[0][3]);
            acc[1][0] = fmaf(a.y, b.x, acc[1][0]); acc[1][1] = fmaf(a.y, b.y, acc[1][1]);
            acc[1][2] = fmaf(a.y, b.z, acc[1][2]); acc[1][3] = fmaf(a.y, b.w, acc[1][3]);
            acc[2][0] = fmaf(a.z, b.x, acc[2][0]); acc[2][1] = fmaf(a.z, b.y, acc[2][1]);
            acc[2][2] = fmaf(a.z, b.z, acc[2][2]); acc[2][3] = fmaf(a.z, b.w, acc[2][3]);
            acc[3][0] = fmaf(a.w, b.x, acc[3][0]); acc[3][1] = fmaf(a.w, b.y, acc[3][1]);
            acc[3][2] = fmaf(a.w, b.z, acc[3][2]); acc[3][3] = fmaf(a.w, b.w, acc[3][3]);
        }
        __syncthreads();
    }

#pragma unroll
    for (int i = 0; i < 4; ++i) {
        const size_t row = (size_t)(m0 + ty * 4 + i) * N + n0 + tx * 4;
#pragma unroll
        for (int j = 0; j < 4; ++j)
            C[row + j] = acc[i][j] + __ldg(&bias[n0 + tx * 4 + j]);
    }
}

// =====================================================================
// Head GEMM: C[M][256] = A[M][512] @ B[256][512]^T + bias
// 64x128 tile, BK=16, microtile 4m x 8n (f32x2), 2 CTAs/SM.
// =====================================================================
__global__ __launch_bounds__(256, 2)
void gemm_head_f32x2(const float* __restrict__ A,
                     const float* __restrict__ Bm,
                     const float* __restrict__ bias,
                     float* __restrict__ C)
{
    __shared__ float As[16][68];
    __shared__ float Bs[16][136];

    const int tid  = threadIdx.x;
    const int m0   = blockIdx.x * 64;
    const int n0   = blockIdx.y * 128;
    const int arow = tid >> 2;
    const int acol = (tid & 3) * 4;
    const int brow = tid >> 1;
    const int bcol = (tid & 1) * 4;
    const int tx   = tid & 15;
    const int ty   = tid >> 4;

    ull acc[4][4];
#pragma unroll
    for (int i = 0; i < 4; ++i)
#pragma unroll
        for (int j = 0; j < 4; ++j) acc[i][j] = 0ull;

    for (int k0 = 0; k0 < 512; k0 += 16) {
        {
            float4 av = *reinterpret_cast<const float4*>(A + (size_t)(m0 + arow) * 512 + k0 + acol);
            As[acol + 0][arow] = av.x;  As[acol + 1][arow] = av.y;
            As[acol + 2][arow] = av.z;  As[acol + 3][arow] = av.w;
            float4 b0 = *reinterpret_cast<const float4*>(Bm + (size_t)(n0 + brow) * 512 + k0 + bcol);
            float4 b1 = *reinterpret_cast<const float4*>(Bm + (size_t)(n0 + brow) * 512 + k0 + bcol + 8);
            Bs[bcol + 0][brow] = b0.x;  Bs[bcol + 1][brow] = b0.y;
            Bs[bcol + 2][brow] = b0.z;  Bs[bcol + 3][brow] = b0.w;
            Bs[bcol + 8][brow] = b1.x;  Bs[bcol + 9][brow] = b1.y;
            Bs[bcol + 10][brow] = b1.z; Bs[bcol + 11][brow] = b1.w;
        }
        __syncthreads();
#pragma unroll
        for (int kk = 0; kk < 16; ++kk) {
            const float4 a = *reinterpret_cast<const float4*>(&As[kk][ty * 4]);
            const ulonglong2 bA = *reinterpret_cast<const ulonglong2*>(&Bs[kk][tx * 8]);
            const ulonglong2 bB = *reinterpret_cast<const ulonglong2*>(&Bs[kk][tx * 8 + 4]);
            ull ad0 = fdup(a.x), ad1 = fdup(a.y), ad2 = fdup(a.z), ad3 = fdup(a.w);
            acc[0][0] = ffma2(ad0, bA.x, acc[0][0]); acc[0][1] = ffma2(ad0, bA.y, acc[0][1]);
            acc[0][2] = ffma2(ad0, bB.x, acc[0][2]); acc[0][3] = ffma2(ad0, bB.y, acc[0][3]);
            acc[1][0] = ffma2(ad1, bA.x, acc[1][0]); acc[1][1] = ffma2(ad1, bA.y, acc[1][1]);
            acc[1][2] = ffma2(ad1, bB.x, acc[1][2]); acc[1][3] = ffma2(ad1, bB.y, acc[1][3]);
            acc[2][0] = ffma2(ad2, bA.x, acc[2][0]); acc[2][1] = ffma2(ad2, bA.y, acc[2][1]);
            acc[2][2] = ffma2(ad2, bB.x, acc[2][2]); acc[2][3] = ffma2(ad2, bB.y, acc[2][3]);
            acc[3][0] = ffma2(ad3, bA.x, acc[3][0]); acc[3][1] = ffma2(ad3, bA.y, acc[3][1]);
            acc[3][2] = ffma2(ad3, bB.x, acc[3][2]); acc[3][3] = ffma2(ad3, bB.y, acc[3][3]);
        }
        __syncthreads();
    }

    const float4 bi0 = *reinterpret_cast<const float4*>(bias + n0 + tx * 8);
    const float4 bi1 = *reinterpret_cast<const float4*>(bias + n0 + tx * 8 + 4);
#pragma unroll
    for (int i = 0; i < 4; ++i) {
        float* crow = C + (size_t)(m0 + ty * 4 + i) * 256 + n0 + tx * 8;
        const float2 p0 = unpack2(acc[i][0]);
        const float2 p1 = unpack2(acc[i][1]);
        const float2 p2 = unpack2(acc[i][2]);
        const float2 p3 = unpack2(acc[i][3]);
        float4 o0 = make_float4(p0.x + bi0.x, p0.y + bi0.y, p1.x + bi0.z, p1.y + bi0.w);
        float4 o1 = make_float4(p2.x + bi1.x, p2.y + bi1.y, p3.x + bi1.z, p3.y + bi1.w);
        *reinterpret_cast<float4*>(crow)     = o0;
        *reinterpret_cast<float4*>(crow + 4) = o1;
    }
}

// =====================================================================
// Persistent recurrence with clusters + DSMEM.
// grid = 128 CTAs = 16 clusters x 8 CTAs.
// Cluster = 4 batches; CTA = 64 outputs; thread (eg in 4, o in 64) holds
// W_h[o0+o][eg*128..+128) in 64 f32x2 registers.
// Per step: compute partials from double-buffered hsm (broadcast LDS),
// smem-reduce over 4 eg, tanh, push h to 7 peers via st.shared::cluster
// (SKIPPED on the last step - no remote stores may be in flight at exit),
// fire-and-forget STCG to g_hs, one barrier.cluster per step.
// =====================================================================
#define HPAD 520

__global__ __launch_bounds__(256, 1) __cluster_dims__(8, 1, 1)
void rnn_scan(const int* __restrict__ x,
              const float* __restrict__ h0,
              const float* __restrict__ w_cell)
{
    __shared__ float hsm[2][4][HPAD];    // double-buffered h: [buf][b][e]
    __shared__ float red[4 * 256];       // [b][eg][o] = b*256 + eg*64 + o

    const int tid = threadIdx.x;
    uint32_t rank;
    asm("mov.u32 %0, %%cluster_ctarank;" : "=r"(rank));
    const int cid = blockIdx.x >> 3;     // cluster id 0..15
    const int b0  = cid * 4;             // batch base
    const int o0  = (int)rank * 64;      // output base

    const int o  = tid & 63;             // output lane
    const int eg = tid >> 6;             // e-chunk id (128 e each)

    // ---- W_h chunk into registers as f32x2 pairs (once) ----
    ull w2[64];
    {
        const float* wrow = w_cell + (size_t)(o0 + o) * 1024 + 512 + eg * 128;
#pragma unroll
        for (int p = 0; p < 64; ++p)
            w2[p] = *reinterpret_cast<const ull*>(wrow + 2 * p);
    }

    // reduce/output mapping
    const int rb = tid >> 6;             // batch 0..3
    const int ro = tid & 63;             // local out 0..63
    const int og = o0 + ro;              // global out

    // ---- init hsm[0] with h0 broadcast ----
    for (int i = tid; i < 4 * 512; i += 256) {
        const int b = i >> 9;
        const int e = i & 511;
        hsm[0][b][e] = __ldg(&h0[e]);
    }
    __syncthreads();

    for (int t = 0; t < TT; ++t) {
        const int p = t & 1;
        const int q = p ^ 1;

        // prefetch token + input projection (consumed after compute)
        const int   xv = __ldg(x + (size_t)(b0 + rb) * TT + t);
        const float xw = __ldg(&g_xwv[(size_t)xv * EE + og]);

        // ---- compute: 4 batches x (128-e dot) per thread ----
#pragma unroll
        for (int b = 0; b < 4; ++b) {
            const float* hb = &hsm[p][b][eg * 128];
            ull a0 = 0ull, a1 = 0ull;
#pragma unroll
            for (int j = 0; j < 32; ++j) {
                const ulonglong2 hv = *reinterpret_cast<const ulonglong2*>(hb + j * 4);
                a0 = ffma2(hv.x, w2[2 * j + 0], a0);
                a1 = ffma2(hv.y, w2[2 * j + 1], a1);
            }
            const float2 s0 = unpack2(a0);
            const float2 s1 = unpack2(a1);
            red[b * 256 + eg * 64 + o] = (s0.x + s1.x) + (s0.y + s1.y);
        }
        __syncthreads();

        // ---- reduce over 4 eg chunks, tanh ----
        const float sum = red[rb * 256 +   0 + ro] + red[rb * 256 +  64 + ro]
                        + red[rb * 256 + 128 + ro] + red[rb * 256 + 192 + ro];
        const float hval = tanhf(sum + xw);

        // ---- push h into next buffer (self + 7 peers) - NOT on last step ----
        if (t < TT - 1) {
            hsm[q][rb][og] = hval;
            const uint32_t laddr = smem_u32(&hsm[q][rb][og]);
#pragma unroll
            for (int r = 1; r < 8; ++r) {
                const uint32_t pr = (rank + (uint32_t)r) & 7u;
                uint32_t raddr;
                asm volatile("mapa.shared::cluster.u32 %0, %1, %2;"
                             : "=r"(raddr) : "r"(laddr), "r"(pr));
                asm volatile("st.shared::cluster.f32 [%0], %1;"
                             :: "r"(raddr), "f"(hval) : "memory");
            }
        }

        // fire-and-forget h store for the head GEMM (off critical path)
        __stcg(&g_hs[((size_t)(b0 + rb) * TT + t) * EE + og], hval);

        // ---- one cluster barrier per step (release/acquire) ----
        if (t < TT - 1) {
            asm volatile("barrier.cluster.arrive.aligned;" ::: "memory");
            asm volatile("barrier.cluster.wait.aligned;"   ::: "memory");
        }
    }

    // safety: no CTA exits while any peer could still target its SMEM
    asm volatile("barrier.cluster.arrive.aligned;" ::: "memory");
    asm volatile("barrier.cluster.wait.aligned;"   ::: "memory");
}

// =====================================================================
// host-side launch
// inputs: 0=x 1=emb 2=w_cell 3=b_cell 4=w_head 5=b_head 6=h0
// =====================================================================
extern "C" void kernel_launch(void* const* d_in, const int* in_sizes, int n_in,
                              void* d_out, int out_size)
{
    const int*   x      = (const int*)  d_in[0];
    const float* emb    = (const float*)d_in[1];
    const float* w_cell = (const float*)d_in[2];
    const float* b_cell = (const float*)d_in[3];
    const float* w_head = (const float*)d_in[4];
    const float* b_head = (const float*)d_in[5];
    const float* h0     = (const float*)d_in[6];
    float*       out    = (float*)d_out;

    void* p_xwv = nullptr;
    void* p_hs  = nullptr;
    cudaGetSymbolAddress(&p_xwv, g_xwv);
    cudaGetSymbolAddress(&p_hs,  g_hs);

    // Phase 1: XWV = emb @ w_x^T + b_cell   (256 x 512, K=512)
    {
        dim3 grid(VV / 64, EE / 64);
        gemm_atb<<<grid, 256>>>(emb, EE, w_cell, 2 * EE, b_cell,
                                (float*)p_xwv, EE, EE);
    }

    // Phase 2: recurrence (16 clusters of 8 CTAs)
    rnn_scan<<<128, 256>>>(x, h0, w_cell);

    // Phase 3: head GEMM  out = hs @ w_head^T + b_head
    {
        dim3 grid((BB * TT) / 64, VV / 128);
        gemm_head_f32x2<<<grid, 256>>>((const float*)p_hs, w_head, b_head, out);
    }
}

// round 15
// speedup vs baseline: 1.4638x; 1.4638x over previous
#include <cuda_runtime.h>
#include <cstdint>

#define BB 64      // batch
#define TT 1024    // time steps
#define EE 512     // embedding
#define VV 256     // vocab

typedef unsigned long long ull;

// ---------------- device scratch ----------------
__device__ float g_xwv[VV * EE];                 // XWV[v][o] = emb[v]·w_x[o] + b_cell[o]
__device__ float g_hs[(size_t)BB * TT * EE];     // h_t, layout [b][t][e]  (128 MB)
__device__ unsigned int g_bar[16 * 32];          // per-group counter, 128B apart

// ---------------- helpers ----------------
__device__ __forceinline__ ull ffma2(ull a, ull b, ull c) {
    ull d;
    asm("fma.rn.f32x2 %0, %1, %2, %3;" : "=l"(d) : "l"(a), "l"(b), "l"(c));
    return d;
}
__device__ __forceinline__ ull fdup(float s) {
    ull d;
    asm("mov.b64 %0, {%1, %1};" : "=l"(d) : "f"(s));
    return d;
}
__device__ __forceinline__ float2 unpack2(ull v) {
    float2 r;
    asm("mov.b64 {%0, %1}, %2;" : "=f"(r.x), "=f"(r.y) : "l"(v));
    return r;
}

// =====================================================================
// Phase-1 GEMM (tiny):  C[M][N] = A[M][K] @ B[N][K]^T + bias[N]
// =====================================================================
__global__ void gemm_atb(const float* __restrict__ A, int lda,
                         const float* __restrict__ Bm, int ldb,
                         const float* __restrict__ bias,
                         float* __restrict__ C, int N, int K)
{
    __shared__ float As[16][64];
    __shared__ float Bs[16][64];

    const int tid  = threadIdx.x;
    const int m0   = blockIdx.x * 64;
    const int n0   = blockIdx.y * 64;
    const int tx   = tid & 15;
    const int ty   = tid >> 4;
    const int lrow = tid >> 2;
    const int lcol = (tid & 3) * 4;

    float acc[4][4];
#pragma unroll
    for (int i = 0; i < 4; ++i)
#pragma unroll
        for (int j = 0; j < 4; ++j) acc[i][j] = 0.0f;

    for (int k0 = 0; k0 < K; k0 += 16) {
        float4 av = *reinterpret_cast<const float4*>(A  + (size_t)(m0 + lrow) * lda + k0 + lcol);
        float4 bv = *reinterpret_cast<const float4*>(Bm + (size_t)(n0 + lrow) * ldb + k0 + lcol);
        As[lcol + 0][lrow] = av.x;  As[lcol + 1][lrow] = av.y;
        As[lcol + 2][lrow] = av.z;  As[lcol + 3][lrow] = av.w;
        Bs[lcol + 0][lrow] = bv.x;  Bs[lcol + 1][lrow] = bv.y;
        Bs[lcol + 2][lrow] = bv.z;  Bs[lcol + 3][lrow] = bv.w;
        __syncthreads();
#pragma unroll
        for (int kk = 0; kk < 16; ++kk) {
            float4 a = *reinterpret_cast<const float4*>(&As[kk][ty * 4]);
            float4 b = *reinterpret_cast<const float4*>(&Bs[kk][tx * 4]);
            acc[0][0] = fmaf(a.x, b.x, acc[0][0]); acc[0][1] = fmaf(a.x, b.y, acc[0][1]);
            acc[0][2] = fmaf(a.x, b.z, acc[0][2]); acc[0][3] = fmaf(a.x, b.w, acc[0][3]);
            acc[1][0] = fmaf(a.y, b.x, acc[1][0]); acc[1][1] = fmaf(a.y, b.y, acc[1][1]);
            acc[1][2] = fmaf(a.y, b.z, acc[1][2]); acc[1][3] = fmaf(a.y, b.w, acc[1][3]);
            acc[2][0] = fmaf(a.z, b.x, acc[2][0]); acc[2][1] = fmaf(a.z, b.y, acc[2][1]);
            acc[2][2] = fmaf(a.z, b.z, acc[2][2]); acc[2][3] = fmaf(a.z, b.w, acc[2][3]);
            acc[3][0] = fmaf(a.w, b.x, acc[3][0]); acc[3][1] = fmaf(a.w, b.y, acc[3][1]);
            acc[3][2] = fmaf(a.w, b.z, acc[3][2]); acc[3][3] = fmaf(a.w, b.w, acc[3][3]);
        }
        __syncthreads();
    }

#pragma unroll
    for (int i = 0; i < 4; ++i) {
        const size_t row = (size_t)(m0 + ty * 4 + i) * N + n0 + tx * 4;
#pragma unroll
        for (int j = 0; j < 4; ++j)
            C[row + j] = acc[i][j] + __ldg(&bias[n0 + tx * 4 + j]);
    }
}

// =====================================================================
// Head GEMM: C[M][256] = A[M][512] @ B[256][512]^T + bias
// 64x128 tile, BK=16, microtile 4m x 8n (f32x2), 2 CTAs/SM.
// =====================================================================
__global__ __launch_bounds__(256, 2)
void gemm_head_f32x2(const float* __restrict__ A,
                     const float* __restrict__ Bm,
                     const float* __restrict__ bias,
                     float* __restrict__ C)
{
    __shared__ float As[16][68];
    __shared__ float Bs[16][136];

    const int tid  = threadIdx.x;
    const int m0   = blockIdx.x * 64;
    const int n0   = blockIdx.y * 128;
    const int arow = tid >> 2;
    const int acol = (tid & 3) * 4;
    const int brow = tid >> 1;
    const int bcol = (tid & 1) * 4;
    const int tx   = tid & 15;
    const int ty   = tid >> 4;

    ull acc[4][4];
#pragma unroll
    for (int i = 0; i < 4; ++i)
#pragma unroll
        for (int j = 0; j < 4; ++j) acc[i][j] = 0ull;

    for (int k0 = 0; k0 < 512; k0 += 16) {
        {
            float4 av = *reinterpret_cast<const float4*>(A + (size_t)(m0 + arow) * 512 + k0 + acol);
            As[acol + 0][arow] = av.x;  As[acol + 1][arow] = av.y;
            As[acol + 2][arow] = av.z;  As[acol + 3][arow] = av.w;
            float4 b0 = *reinterpret_cast<const float4*>(Bm + (size_t)(n0 + brow) * 512 + k0 + bcol);
            float4 b1 = *reinterpret_cast<const float4*>(Bm + (size_t)(n0 + brow) * 512 + k0 + bcol + 8);
            Bs[bcol + 0][brow] = b0.x;  Bs[bcol + 1][brow] = b0.y;
            Bs[bcol + 2][brow] = b0.z;  Bs[bcol + 3][brow] = b0.w;
            Bs[bcol + 8][brow] = b1.x;  Bs[bcol + 9][brow] = b1.y;
            Bs[bcol + 10][brow] = b1.z; Bs[bcol + 11][brow] = b1.w;
        }
        __syncthreads();
#pragma unroll
        for (int kk = 0; kk < 16; ++kk) {
            const float4 a = *reinterpret_cast<const float4*>(&As[kk][ty * 4]);
            const ulonglong2 bA = *reinterpret_cast<const ulonglong2*>(&Bs[kk][tx * 8]);
            const ulonglong2 bB = *reinterpret_cast<const ulonglong2*>(&Bs[kk][tx * 8 + 4]);
            ull ad0 = fdup(a.x), ad1 = fdup(a.y), ad2 = fdup(a.z), ad3 = fdup(a.w);
            acc[0][0] = ffma2(ad0, bA.x, acc[0][0]); acc[0][1] = ffma2(ad0, bA.y, acc[0][1]);
            acc[0][2] = ffma2(ad0, bB.x, acc[0][2]); acc[0][3] = ffma2(ad0, bB.y, acc[0][3]);
            acc[1][0] = ffma2(ad1, bA.x, acc[1][0]); acc[1][1] = ffma2(ad1, bA.y, acc[1][1]);
            acc[1][2] = ffma2(ad1, bB.x, acc[1][2]); acc[1][3] = ffma2(ad1, bB.y, acc[1][3]);
            acc[2][0] = ffma2(ad2, bA.x, acc[2][0]); acc[2][1] = ffma2(ad2, bA.y, acc[2][1]);
            acc[2][2] = ffma2(ad2, bB.x, acc[2][2]); acc[2][3] = ffma2(ad2, bB.y, acc[2][3]);
            acc[3][0] = ffma2(ad3, bA.x, acc[3][0]); acc[3][1] = ffma2(ad3, bA.y, acc[3][1]);
            acc[3][2] = ffma2(ad3, bB.x, acc[3][2]); acc[3][3] = ffma2(ad3, bB.y, acc[3][3]);
        }
        __syncthreads();
    }

    const float4 bi0 = *reinterpret_cast<const float4*>(bias + n0 + tx * 8);
    const float4 bi1 = *reinterpret_cast<const float4*>(bias + n0 + tx * 8 + 4);
#pragma unroll
    for (int i = 0; i < 4; ++i) {
        float* crow = C + (size_t)(m0 + ty * 4 + i) * 256 + n0 + tx * 8;
        const float2 p0 = unpack2(acc[i][0]);
        const float2 p1 = unpack2(acc[i][1]);
        const float2 p2 = unpack2(acc[i][2]);
        const float2 p3 = unpack2(acc[i][3]);
        float4 o0 = make_float4(p0.x + bi0.x, p0.y + bi0.y, p1.x + bi0.z, p1.y + bi0.w);
        float4 o1 = make_float4(p2.x + bi1.x, p2.y + bi1.y, p3.x + bi1.z, p3.y + bi1.w);
        *reinterpret_cast<float4*>(crow)     = o0;
        *reinterpret_cast<float4*>(crow + 4) = o1;
    }
}

// =====================================================================
__global__ void reset_bar()
{
    if (threadIdx.x < 16) g_bar[threadIdx.x * 32] = 0u;
}

// =====================================================================
// Persistent recurrence. grid = 128 CTAs = 16 groups x 8 CTAs (L2 sync).
// Group = 4 batches; CTA = 64 outputs; thread (eg in 4, o in 64) holds
// W_h[o0+o][eg*128..+128) in 64 f32x2 registers.
// Per step: compute partials from hsm (broadcast LDS), smem-reduce over
// 4 eg, tanh, STCG h to L2, 8-arrival release/acquire counter barrier,
// reload group h (8KB) from L2 into hsm. Token stream pre-staged in smem.
// =====================================================================
__global__ __launch_bounds__(256, 1)
void rnn_scan(const int* __restrict__ x,
              const float* __restrict__ h0,
              const float* __restrict__ w_cell)
{
    __shared__ float hsm[4][EE];        // h_prev: [b][e]
    __shared__ float red[4 * 256];      // [b][eg][o] = b*256 + eg*64 + o
    __shared__ int   xsm[4][TT];        // token stream for this group's batches

    const int tid = threadIdx.x;
    const int gid = blockIdx.x >> 3;    // group 0..15
    const int b0  = gid * 4;            // batch base
    const int o0  = (blockIdx.x & 7) * 64;   // output base

    const int o  = tid & 63;            // output lane
    const int eg = tid >> 6;            // e-chunk id (128 e each)

    // ---- W_h chunk into registers as f32x2 pairs (once) ----
    ull w2[64];
    {
        const float* wrow = w_cell + (size_t)(o0 + o) * 1024 + 512 + eg * 128;
#pragma unroll
        for (int p = 0; p < 64; ++p)
            w2[p] = *reinterpret_cast<const ull*>(wrow + 2 * p);
    }

    // ---- stage token stream: 4 batches x 1024 ints = 16KB ----
    {
        int4* xd = reinterpret_cast<int4*>(&xsm[0][0]);
        const int4* xs = reinterpret_cast<const int4*>(x + (size_t)b0 * TT);
        for (int i = tid; i < 1024; i += 256) xd[i] = __ldg(&xs[i]);
    }

    // reduce/output mapping
    const int rb = tid >> 6;            // batch 0..3
    const int ro = tid & 63;            // local out 0..63
    const int og = o0 + ro;             // global out

    // staging mapping: thread loads 8 floats of one batch row
    const int lb = tid >> 6;            // batch 0..3
    const int e0 = (tid & 63) * 8;      // e base

    // ---- init hsm with h0 ----
    for (int i = tid; i < 4 * EE; i += 256)
        hsm[i >> 9][i & 511] = __ldg(&h0[i & 511]);
    __syncthreads();

    const unsigned long long bar_ga =
        __cvta_generic_to_global((void*)&g_bar[gid * 32]);

    for (int t = 0; t < TT; ++t) {
        // token + input projection (xsm broadcast; xwv coalesced, L1/L2 hit)
        const int   xv = xsm[rb][t];
        const float xw = __ldg(&g_xwv[(size_t)xv * EE + og]);

        // ---- compute: 4 batches x (128-e dot) per thread ----
#pragma unroll
        for (int b = 0; b < 4; ++b) {
            const float* hb = &hsm[b][eg * 128];
            ull a0 = 0ull, a1 = 0ull;
#pragma unroll
            for (int j = 0; j < 32; ++j) {
                const ulonglong2 hv = *reinterpret_cast<const ulonglong2*>(hb + j * 4);
                a0 = ffma2(hv.x, w2[2 * j + 0], a0);
                a1 = ffma2(hv.y, w2[2 * j + 1], a1);
            }
            const float2 s0 = unpack2(a0);
            const float2 s1 = unpack2(a1);
            red[b * 256 + eg * 64 + o] = (s0.x + s1.x) + (s0.y + s1.y);
        }
        __syncthreads();

        // ---- reduce over 4 eg chunks, tanh, publish h through L2 ----
        const float sum = red[rb * 256 +   0 + ro] + red[rb * 256 +  64 + ro]
                        + red[rb * 256 + 128 + ro] + red[rb * 256 + 192 + ro];
        const float hval = tanhf(sum + xw);
        __stcg(&g_hs[((size_t)(b0 + rb) * TT + t) * EE + og], hval);

        if (t < TT - 1) {
            // ---- 8-arrival group barrier: release-add / acquire-spin ----
            __syncthreads();
            if (tid == 0) {
                const unsigned int target = 8u * (unsigned int)(t + 1);
                unsigned int prev;
                asm volatile("atom.add.release.gpu.global.u32 %0, [%1], %2;"
                             : "=r"(prev) : "l"(bar_ga), "r"(1u) : "memory");
                if (prev + 1u < target) {
                    unsigned int cur;
                    do {
                        asm volatile("ld.acquire.gpu.global.u32 %0, [%1];"
                                     : "=r"(cur) : "l"(bar_ga) : "memory");
                    } while (cur < target);
                }
            }
            __syncthreads();

            // ---- reload full group h(t) into hsm (8KB from L2) ----
            {
                const float* src = g_hs + ((size_t)(b0 + lb) * TT + t) * EE + e0;
                const float4 v0 = __ldcg(reinterpret_cast<const float4*>(src));
                const float4 v1 = __ldcg(reinterpret_cast<const float4*>(src + 4));
                *reinterpret_cast<float4*>(&hsm[lb][e0])     = v0;
                *reinterpret_cast<float4*>(&hsm[lb][e0 + 4]) = v1;
            }
            __syncthreads();
        }
    }
}

// =====================================================================
// host-side launch
// inputs: 0=x 1=emb 2=w_cell 3=b_cell 4=w_head 5=b_head 6=h0
// =====================================================================
extern "C" void kernel_launch(void* const* d_in, const int* in_sizes, int n_in,
                              void* d_out, int out_size)
{
    const int*   x      = (const int*)  d_in[0];
    const float* emb    = (const float*)d_in[1];
    const float* w_cell = (const float*)d_in[2];
    const float* b_cell = (const float*)d_in[3];
    const float* w_head = (const float*)d_in[4];
    const float* b_head = (const float*)d_in[5];
    const float* h0     = (const float*)d_in[6];
    float*       out    = (float*)d_out;

    void* p_xwv = nullptr;
    void* p_hs  = nullptr;
    cudaGetSymbolAddress(&p_xwv, g_xwv);
    cudaGetSymbolAddress(&p_hs,  g_hs);

    // Phase 1: XWV = emb @ w_x^T + b_cell   (256 x 512, K=512)
    {
        dim3 grid(VV / 64, EE / 64);
        gemm_atb<<<grid, 256>>>(emb, EE, w_cell, 2 * EE, b_cell,
                                (float*)p_xwv, EE, EE);
    }

    // Phase 2: recurrence (16 groups of 8 CTAs, L2 sync)
    reset_bar<<<1, 32>>>();
    rnn_scan<<<128, 256>>>(x, h0, w_cell);

    // Phase 3: head GEMM  out = hs @ w_head^T + b_head
    {
        dim3 grid((BB * TT) / 64, VV / 128);
        gemm_head_f32x2<<<grid, 256>>>((const float*)p_hs, w_head, b_head, out);
    }
}